// round 14
// baseline (speedup 1.0000x reference)
#include <cuda_runtime.h>
#include <cuda_fp16.h>
#include <cstdint>
#include <math.h>

// Problem constants (fixed by setup_inputs).
#define NSUP   1024
#define NQRY   1024
#define DDIM   128
#define HDIM   64
#define NWAY   8
#define QTILE  128
#define SCHUNK 57
#define NSB    18           // ceil(1024/57); grid 8 x 18 = 144 CTAs = exactly 1 wave
#define NTHR   512

// Per-CTA partial sums: [qb*NSB + sb][class][q] -- fully written, no init needed.
__device__ float    g_part[(NQRY / QTILE) * NSB * NWAY * QTILE];
// Per-q-column completion tickets. atomicInc with wrap NSB-1 -> back to 0 after
// every launch (exactly NSB increments per column), so graph replays see 0.
__device__ unsigned g_tick[NQRY / QTILE];

// ---------------- helpers ----------------------------------------------------
__device__ __forceinline__ uint32_t h2u(__half2 h) {
    return *reinterpret_cast<uint32_t*>(&h);
}
__device__ __forceinline__ uint32_t absdiff2(uint32_t q, __half2 s) {
    __half2 hq = *reinterpret_cast<__half2*>(&q);
    return h2u(__habs2(__hsub2(hq, s)));
}
__device__ __forceinline__ void mma16816(float* d, uint32_t a0, uint32_t a1,
                                         uint32_t a2, uint32_t a3,
                                         uint32_t b0, uint32_t b1) {
    asm volatile(
        "mma.sync.aligned.m16n8k16.row.col.f32.f16.f16.f32 "
        "{%0,%1,%2,%3}, {%4,%5,%6,%7}, {%8,%9}, {%0,%1,%2,%3};"
        : "+f"(d[0]), "+f"(d[1]), "+f"(d[2]), "+f"(d[3])
        : "r"(a0), "r"(a1), "r"(a2), "r"(a3), "r"(b0), "r"(b1));
}

// ---------------- single fused kernel ------------------------------------------
// CTA: 128-q block x 57-s chunk, 512 threads = 16 warps, grid 8x18 = one wave.
// Warp (mi, nj): mi in 0..7 = 16-row m-slice, nj in 0..1 = 32-col n-slice.
// Warp tile m16 x n32 x k128: Bf 64 regs + qh 32 regs + D 16 regs -> fits the
// 128-reg cap, giving 4 warps per SMSP to hide HMMA/LDS latency.
__global__ __launch_bounds__(NTHR, 1) void pairs_kernel(
    const float* __restrict__ qx, const float* __restrict__ sx,
    const float* __restrict__ W1, const float* __restrict__ b1,
    const float* __restrict__ w2v, const float* __restrict__ b2g,
    const void* __restrict__ sy_raw, float* __restrict__ out) {
    __shared__ __half2  s_sm[SCHUNK * 64];          // s chunk, fp16x2 (14.25KB)
    __shared__ float    accf[2 * NWAY * QTILE];     // [nj][class][q]; reused as logits
    __shared__ float    b1s[HDIM], w2s[HDIM];
    __shared__ int      slab[SCHUNK];
    __shared__ int      s_is64;
    __shared__ unsigned s_old;
    __shared__ float    s_hist[16][NWAY];

    const int tid  = threadIdx.x;
    const int lane = tid & 31;
    const int wid  = tid >> 5;        // 0..15
    const int mi   = wid & 7;         // 16-row m-slice
    const int nj   = wid >> 3;        // 32-col n-slice
    const int g    = lane >> 2;       // row-in-8 group
    const int i2   = lane & 3;        // k quad position
    const int q0   = blockIdx.x * QTILE;
    const int s0   = blockIdx.y * SCHUNK;
    const int ns   = min(SCHUNK, NSUP - s0);

    if (tid == 0) s_is64 = 1;
    for (int idx = tid; idx < 2 * NWAY * QTILE; idx += NTHR) accf[idx] = 0.0f;
    if (tid < HDIM) {
        b1s[tid] = b1[tid];
        w2s[tid] = w2v[tid];
    }
    __syncthreads();

    // int64-vs-int32 detection for support_y (odd words all zero => int64).
    const int* sy32 = (const int*)sy_raw;
    if (sy32[2 * tid + 1] != 0) atomicExch(&s_is64, 0);

    // Stage s chunk as half2 (row = 64 half2 = 256B).
    for (int idx = tid; idx < ns * 64; idx += NTHR) {
        int r = idx >> 6, c = idx & 63;
        float2 v = *(const float2*)(sx + (size_t)(s0 + r) * DDIM + 2 * c);
        s_sm[idx] = __floats2half2_rn(v.x, v.y);
    }
    __syncthreads();

    const int is64 = s_is64;
    const long long* sy64 = (const long long*)sy_raw;
    for (int idx = tid; idx < ns; idx += NTHR)
        slab[idx] = is64 ? (int)sy64[s0 + idx] : sy32[s0 + idx];

    // ---- q fragment values in registers: qh[ri][kb][h], rows mi*16+g+ri*8 ----
    uint32_t qh[2][8][2];
#pragma unroll
    for (int ri = 0; ri < 2; ++ri) {
        const float* qp = qx + (size_t)(q0 + mi * 16 + g + ri * 8) * DDIM + i2 * 2;
#pragma unroll
        for (int kb = 0; kb < 8; ++kb) {
            float2 v0 = *(const float2*)(qp + kb * 16);
            float2 v1 = *(const float2*)(qp + kb * 16 + 8);
            qh[ri][kb][0] = h2u(__floats2half2_rn(v0.x, v0.y));
            qh[ri][kb][1] = h2u(__floats2half2_rn(v1.x, v1.y));
        }
    }

    // ---- W1 B-fragments in registers (warp covers cols nj*32..+31) ----
    uint32_t Bf[4][8][2];
#pragma unroll
    for (int nb = 0; nb < 4; ++nb) {
        const float* wr = W1 + (size_t)(nj * 32 + nb * 8 + g) * DDIM + i2 * 2;
#pragma unroll
        for (int kb = 0; kb < 8; ++kb) {
            float2 v0 = *(const float2*)(wr + kb * 16);
            float2 v1 = *(const float2*)(wr + kb * 16 + 8);
            Bf[nb][kb][0] = h2u(__floats2half2_rn(v0.x, v0.y));
            Bf[nb][kb][1] = h2u(__floats2half2_rn(v1.x, v1.y));
        }
    }

    __syncthreads();   // slab ready (s_sm already synced)

    // ---- main loop: one s row per iteration; no barriers inside ----
    for (int i = 0; i < ns; ++i) {
        const __half2* srow = s_sm + i * 64;

        float D[4][4];
#pragma unroll
        for (int nb = 0; nb < 4; ++nb)
#pragma unroll
            for (int c = 0; c < 4; ++c) D[nb][c] = 0.0f;

#pragma unroll
        for (int kb = 0; kb < 8; ++kb) {
            __half2 hs0 = srow[kb * 8 + i2];
            __half2 hs1 = srow[kb * 8 + 4 + i2];
            uint32_t a0 = absdiff2(qh[0][kb][0], hs0);
            uint32_t a1 = absdiff2(qh[1][kb][0], hs0);
            uint32_t a2 = absdiff2(qh[0][kb][1], hs1);
            uint32_t a3 = absdiff2(qh[1][kb][1], hs1);
#pragma unroll
            for (int nb = 0; nb < 4; ++nb)
                mma16816(D[nb], a0, a1, a2, a3, Bf[nb][kb][0], Bf[nb][kb][1]);
        }

        // Epilogue: sim contribution = sum_n relu(D + b1) * w2 for this slice.
        const int lab = slab[i];
        float p0 = 0.0f, p1 = 0.0f;
#pragma unroll
        for (int nb = 0; nb < 4; ++nb) {
            const int col = nj * 32 + nb * 8 + i2 * 2;
            float bb0 = b1s[col], bb1 = b1s[col + 1];
            float ww0 = w2s[col], ww1 = w2s[col + 1];
            p0 = fmaf(fmaxf(D[nb][0] + bb0, 0.0f), ww0, p0);
            p0 = fmaf(fmaxf(D[nb][1] + bb1, 0.0f), ww1, p0);
            p1 = fmaf(fmaxf(D[nb][2] + bb0, 0.0f), ww0, p1);
            p1 = fmaf(fmaxf(D[nb][3] + bb1, 0.0f), ww1, p1);
        }
        p0 += __shfl_xor_sync(0xffffffffu, p0, 1);
        p0 += __shfl_xor_sync(0xffffffffu, p0, 2);
        p1 += __shfl_xor_sync(0xffffffffu, p1, 1);
        p1 += __shfl_xor_sync(0xffffffffu, p1, 2);
        if (i2 == 0) {
            int r0 = mi * 16 + g;                 // unique (mi, g) per nj half
            accf[nj * (NWAY * QTILE) + lab * QTILE + r0]     += p0;
            accf[nj * (NWAY * QTILE) + lab * QTILE + r0 + 8] += p1;
        }
    }

    __syncthreads();
    // Flush per-CTA partials (merge n-halves); unique g_part slice per CTA.
    float* dst = g_part + (size_t)(blockIdx.x * NSB + blockIdx.y) * (NWAY * QTILE);
    for (int idx = tid; idx < NWAY * QTILE; idx += NTHR)
        dst[idx] = accf[idx] + accf[NWAY * QTILE + idx];
    __syncthreads();

    // Ticket: last CTA in this q-column becomes the reducer.
    if (tid == 0) {
        __threadfence();
        s_old = atomicInc(&g_tick[blockIdx.x], NSB - 1);
    }
    __syncthreads();
    if (s_old != NSB - 1) return;

    // ================= reducer path (one CTA per q-column) ==================
    // Label histogram: warp w covers labels [w*64, w*64+64) in registers.
    {
        float cnt[NWAY];
#pragma unroll
        for (int m = 0; m < NWAY; ++m) cnt[m] = 0.0f;
#pragma unroll
        for (int k = 0; k < 2; ++k) {
            int i = wid * 64 + k * 32 + lane;
            int lab = is64 ? (int)sy64[i] : sy32[i];
#pragma unroll
            for (int m = 0; m < NWAY; ++m) cnt[m] += (lab == m) ? 1.0f : 0.0f;
        }
#pragma unroll
        for (int m = 0; m < NWAY; ++m) {
            cnt[m] += __shfl_xor_sync(0xffffffffu, cnt[m], 16);
            cnt[m] += __shfl_xor_sync(0xffffffffu, cnt[m], 8);
            cnt[m] += __shfl_xor_sync(0xffffffffu, cnt[m], 4);
            cnt[m] += __shfl_xor_sync(0xffffffffu, cnt[m], 2);
            cnt[m] += __shfl_xor_sync(0xffffffffu, cnt[m], 1);
        }
        if (lane < NWAY) s_hist[wid][lane] = cnt[lane];
    }
    __syncthreads();

    // Reduce 18 partials per (q, class); 2 outputs per thread, coalesced over q.
    float* logit = accf;             // reuse smem: [q][class]
    const float b2v = b2g[0];
#pragma unroll
    for (int j = 0; j < 2; ++j) {
        const int idx = tid + NTHR * j;
        const int c = idx >> 7, qi = idx & 127;
        const float* p = g_part + ((size_t)(blockIdx.x * NSB) * NWAY + c) * QTILE + qi;
        float a = 0.0f;
#pragma unroll
        for (int sb = 0; sb < NSB; ++sb) a += p[(size_t)sb * (NWAY * QTILE)];
        float cn = 0.0f;
#pragma unroll
        for (int w = 0; w < 16; ++w) cn += s_hist[w][c];
        logit[qi * NWAY + c] = a / cn + b2v;
    }
    __syncthreads();

    // log_softmax: one q per thread (threads 0..127).
    if (tid < QTILE) {
        float l[NWAY], mx = -1e30f;
#pragma unroll
        for (int k = 0; k < NWAY; ++k) {
            l[k] = logit[tid * NWAY + k];
            mx = fmaxf(mx, l[k]);
        }
        float s = 0.0f;
#pragma unroll
        for (int k = 0; k < NWAY; ++k) s += expf(l[k] - mx);
        const float ls = logf(s);
        float* o = out + (size_t)(q0 + tid) * NWAY;
#pragma unroll
        for (int k = 0; k < NWAY; ++k) o[k] = l[k] - mx - ls;
    }
}

// ---------------- launch --------------------------------------------------------
extern "C" void kernel_launch(void* const* d_in, const int* in_sizes, int n_in,
                              void* d_out, int out_size) {
    (void)in_sizes; (void)out_size;
    const float* support_x = (const float*)d_in[0];
    const void*  support_y = d_in[1];
    const float* query_x   = (const float*)d_in[2];
    int base = (n_in >= 8) ? 4 : 3;   // n_way scalar may or may not be marshalled
    const float* W1 = (const float*)d_in[base + 0];
    const float* b1 = (const float*)d_in[base + 1];
    const float* W2 = (const float*)d_in[base + 2];
    const float* b2 = (const float*)d_in[base + 3];
    float* out = (float*)d_out;

    pairs_kernel<<<dim3(NQRY / QTILE, NSB), NTHR>>>(query_x, support_x, W1, b1, W2,
                                                    b2, support_y, out);
}

// round 15
// speedup vs baseline: 1.0708x; 1.0708x over previous
#include <cuda_runtime.h>
#include <cuda_fp16.h>
#include <cstdint>
#include <math.h>

// Problem constants (fixed by setup_inputs).
#define NSUP   1024
#define NQRY   1024
#define DDIM   128
#define HDIM   64
#define NWAY   8
#define QTILE  128
#define SCHUNK 57
#define NSB    18           // ceil(1024/57); grid 8 x 18 = 144 CTAs = exactly 1 wave

// Per-CTA partial sums: [qb*NSB + sb][class][q] -- fully written, no init needed.
__device__ float    g_part[(NQRY / QTILE) * NSB * NWAY * QTILE];
// Per-q-column completion tickets. atomicInc with wrap NSB-1 -> back to 0 after
// every launch (exactly NSB increments per column), so graph replays see 0.
__device__ unsigned g_tick[NQRY / QTILE];

// ---------------- helpers ----------------------------------------------------
__device__ __forceinline__ uint32_t h2u(__half2 h) {
    return *reinterpret_cast<uint32_t*>(&h);
}
__device__ __forceinline__ uint32_t absdiff2(uint32_t q, uint32_t s) {
    __half2 hq = *reinterpret_cast<__half2*>(&q);
    __half2 hs = *reinterpret_cast<__half2*>(&s);
    return h2u(__habs2(__hsub2(hq, hs)));
}
__device__ __forceinline__ void mma16816(float* d, uint32_t a0, uint32_t a1,
                                         uint32_t a2, uint32_t a3,
                                         uint32_t b0, uint32_t b1) {
    asm volatile(
        "mma.sync.aligned.m16n8k16.row.col.f32.f16.f16.f32 "
        "{%0,%1,%2,%3}, {%4,%5,%6,%7}, {%8,%9}, {%0,%1,%2,%3};"
        : "+f"(d[0]), "+f"(d[1]), "+f"(d[2]), "+f"(d[3])
        : "r"(a0), "r"(a1), "r"(a2), "r"(a3), "r"(b0), "r"(b1));
}

// ---------------- single fused kernel ------------------------------------------
// CTA: 128-q block x 57-s chunk, 256 threads, grid 8x18 = one full wave.
// Warp (mi, nj): mi = 32-row m-slice, nj = 32-col n-slice. A fragments computed
// directly in registers. Current s-row held in a 16-reg buffer; next s-row is
// prefetched after the HMMA block so the epilogue hides the LDS latency.
__global__ __launch_bounds__(256, 1) void pairs_kernel(
    const float* __restrict__ qx, const float* __restrict__ sx,
    const float* __restrict__ W1, const float* __restrict__ b1,
    const float* __restrict__ w2v, const float* __restrict__ b2g,
    const void* __restrict__ sy_raw, float* __restrict__ out) {
    __shared__ __half2  s_sm[SCHUNK * 64];          // s chunk, fp16x2 (14.25KB)
    __shared__ float    accf[2 * NWAY * QTILE];     // [nj][class][q]; reused as logits
    __shared__ int      slab[SCHUNK];
    __shared__ int      s_is64;
    __shared__ unsigned s_old;
    __shared__ float    s_hist[8][NWAY];

    const int tid  = threadIdx.x;
    const int lane = tid & 31;
    const int wid  = tid >> 5;
    const int mi   = wid & 3;
    const int nj   = wid >> 2;
    const int g    = lane >> 2;       // row-in-8 group
    const int i2   = lane & 3;        // k quad position
    const int q0   = blockIdx.x * QTILE;
    const int s0   = blockIdx.y * SCHUNK;
    const int ns   = min(SCHUNK, NSUP - s0);

    if (tid == 0) s_is64 = 1;
    for (int idx = tid; idx < 2 * NWAY * QTILE; idx += 256) accf[idx] = 0.0f;
    __syncthreads();

    // int64-vs-int32 detection for support_y (odd words all zero => int64).
    const int* sy32 = (const int*)sy_raw;
    if (sy32[2 * tid + 1] != 0) atomicExch(&s_is64, 0);

    // Stage s chunk as half2 (row = 64 half2 = 256B).
    for (int idx = tid; idx < ns * 64; idx += 256) {
        int r = idx >> 6, c = idx & 63;
        float2 v = *(const float2*)(sx + (size_t)(s0 + r) * DDIM + 2 * c);
        s_sm[idx] = __floats2half2_rn(v.x, v.y);
    }
    __syncthreads();

    const int is64 = s_is64;
    const long long* sy64 = (const long long*)sy_raw;
    for (int idx = tid; idx < ns; idx += 256)
        slab[idx] = is64 ? (int)sy64[s0 + idx] : sy32[s0 + idx];

    // ---- q fragment values in registers: qh[ri][kb][h] ----
    uint32_t qh[4][8][2];
#pragma unroll
    for (int ri = 0; ri < 4; ++ri) {
        const float* qp = qx + (size_t)(q0 + mi * 32 + g + ri * 8) * DDIM + i2 * 2;
#pragma unroll
        for (int kb = 0; kb < 8; ++kb) {
            float2 v0 = *(const float2*)(qp + kb * 16);
            float2 v1 = *(const float2*)(qp + kb * 16 + 8);
            qh[ri][kb][0] = h2u(__floats2half2_rn(v0.x, v0.y));
            qh[ri][kb][1] = h2u(__floats2half2_rn(v1.x, v1.y));
        }
    }

    // ---- W1 B-fragments in registers (warp covers cols nj*32..+31) ----
    uint32_t Bf[4][8][2];
#pragma unroll
    for (int nb = 0; nb < 4; ++nb) {
        const float* wr = W1 + (size_t)(nj * 32 + nb * 8 + g) * DDIM + i2 * 2;
#pragma unroll
        for (int kb = 0; kb < 8; ++kb) {
            float2 v0 = *(const float2*)(wr + kb * 16);
            float2 v1 = *(const float2*)(wr + kb * 16 + 8);
            Bf[nb][kb][0] = h2u(__floats2half2_rn(v0.x, v0.y));
            Bf[nb][kb][1] = h2u(__floats2half2_rn(v1.x, v1.y));
        }
    }

    // ---- b1 / w2 for this thread's output columns ----
    float b1r[8], w2r[8];
#pragma unroll
    for (int nb = 0; nb < 4; ++nb)
#pragma unroll
        for (int c = 0; c < 2; ++c) {
            int col = nj * 32 + nb * 8 + i2 * 2 + c;
            b1r[nb * 2 + c] = b1[col];
            w2r[nb * 2 + c] = w2v[col];
        }

    __syncthreads();   // slab ready (s_sm already synced)

    // ---- s-row register buffer: hsc[kb*2+h] = srow[kb*8 + h*4 + i2] ----
    uint32_t hsc[16];
#pragma unroll
    for (int t = 0; t < 16; ++t)
        hsc[t] = h2u(s_sm[(t >> 1) * 8 + (t & 1) * 4 + i2]);

    // ---- main loop: one s row per iteration; no barriers inside ----
    for (int i = 0; i < ns; ++i) {
        // D init = b1 (d0,d1: row g; d2,d3: row g+8 -> same columns/bias).
        float D[2][4][4];
#pragma unroll
        for (int mb = 0; mb < 2; ++mb)
#pragma unroll
            for (int nb = 0; nb < 4; ++nb) {
                D[mb][nb][0] = b1r[nb * 2];
                D[mb][nb][1] = b1r[nb * 2 + 1];
                D[mb][nb][2] = b1r[nb * 2];
                D[mb][nb][3] = b1r[nb * 2 + 1];
            }

#pragma unroll
        for (int kb = 0; kb < 8; ++kb) {
            const uint32_t hs0 = hsc[kb * 2];
            const uint32_t hs1 = hsc[kb * 2 + 1];
#pragma unroll
            for (int mb = 0; mb < 2; ++mb) {
                uint32_t a0 = absdiff2(qh[2 * mb][kb][0], hs0);
                uint32_t a1 = absdiff2(qh[2 * mb + 1][kb][0], hs0);
                uint32_t a2 = absdiff2(qh[2 * mb][kb][1], hs1);
                uint32_t a3 = absdiff2(qh[2 * mb + 1][kb][1], hs1);
#pragma unroll
                for (int nb = 0; nb < 4; ++nb)
                    mma16816(D[mb][nb], a0, a1, a2, a3, Bf[nb][kb][0], Bf[nb][kb][1]);
            }
        }

        // Prefetch next s-row now; epilogue below hides the LDS latency.
        if (i + 1 < ns) {
            const __half2* srn = s_sm + (i + 1) * 64;
#pragma unroll
            for (int t = 0; t < 16; ++t)
                hsc[t] = h2u(srn[(t >> 1) * 8 + (t & 1) * 4 + i2]);
        }

        // Epilogue: sim contribution = sum_n relu(h) * w2 for this warp slice.
        const int lab = slab[i];
#pragma unroll
        for (int mb = 0; mb < 2; ++mb) {
            float p0 = 0.0f, p1 = 0.0f;
#pragma unroll
            for (int nb = 0; nb < 4; ++nb)
#pragma unroll
                for (int c = 0; c < 2; ++c) {
                    p0 = fmaf(fmaxf(D[mb][nb][c],     0.0f), w2r[nb * 2 + c], p0);
                    p1 = fmaf(fmaxf(D[mb][nb][2 + c], 0.0f), w2r[nb * 2 + c], p1);
                }
            p0 += __shfl_xor_sync(0xffffffffu, p0, 1);
            p0 += __shfl_xor_sync(0xffffffffu, p0, 2);
            p1 += __shfl_xor_sync(0xffffffffu, p1, 1);
            p1 += __shfl_xor_sync(0xffffffffu, p1, 2);
            if (i2 == 0) {
                int r0 = mi * 32 + mb * 16 + g;
                accf[nj * (NWAY * QTILE) + lab * QTILE + r0]     += p0;
                accf[nj * (NWAY * QTILE) + lab * QTILE + r0 + 8] += p1;
            }
        }
    }

    __syncthreads();
    // Flush per-CTA partials (merge n-halves); unique g_part slice per CTA.
    float* dst = g_part + (size_t)(blockIdx.x * NSB + blockIdx.y) * (NWAY * QTILE);
    for (int idx = tid; idx < NWAY * QTILE; idx += 256)
        dst[idx] = accf[idx] + accf[NWAY * QTILE + idx];
    __syncthreads();

    // Ticket: last CTA in this q-column becomes the reducer.
    if (tid == 0) {
        __threadfence();
        s_old = atomicInc(&g_tick[blockIdx.x], NSB - 1);
    }
    __syncthreads();
    if (s_old != NSB - 1) return;

    // ================= reducer path (one CTA per q-column) ==================
    // Label histogram: warp w covers labels [w*128, w*128+128) in registers.
    {
        float cnt[NWAY];
#pragma unroll
        for (int m = 0; m < NWAY; ++m) cnt[m] = 0.0f;
#pragma unroll
        for (int k = 0; k < 4; ++k) {
            int i = wid * 128 + k * 32 + lane;
            int lab = is64 ? (int)sy64[i] : sy32[i];
#pragma unroll
            for (int m = 0; m < NWAY; ++m) cnt[m] += (lab == m) ? 1.0f : 0.0f;
        }
#pragma unroll
        for (int m = 0; m < NWAY; ++m) {
            cnt[m] += __shfl_xor_sync(0xffffffffu, cnt[m], 16);
            cnt[m] += __shfl_xor_sync(0xffffffffu, cnt[m], 8);
            cnt[m] += __shfl_xor_sync(0xffffffffu, cnt[m], 4);
            cnt[m] += __shfl_xor_sync(0xffffffffu, cnt[m], 2);
            cnt[m] += __shfl_xor_sync(0xffffffffu, cnt[m], 1);
        }
        if (lane < NWAY) s_hist[wid][lane] = cnt[lane];
    }
    __syncthreads();

    // Reduce 18 partials per (q, class); 4 outputs per thread, coalesced over q.
    float* logit = accf;             // reuse smem: [q][class]
    const float b2v = b2g[0];
#pragma unroll
    for (int j = 0; j < 4; ++j) {
        const int idx = tid + 256 * j;
        const int c = idx >> 7, qi = idx & 127;
        const float* p = g_part + ((size_t)(blockIdx.x * NSB) * NWAY + c) * QTILE + qi;
        float a = 0.0f;
#pragma unroll
        for (int sb = 0; sb < NSB; ++sb) a += p[(size_t)sb * (NWAY * QTILE)];
        float cn = 0.0f;
#pragma unroll
        for (int w = 0; w < 8; ++w) cn += s_hist[w][c];
        logit[qi * NWAY + c] = a / cn + b2v;
    }
    __syncthreads();

    // log_softmax: one q per thread (threads 0..127).
    if (tid < QTILE) {
        float l[NWAY], mx = -1e30f;
#pragma unroll
        for (int k = 0; k < NWAY; ++k) {
            l[k] = logit[tid * NWAY + k];
            mx = fmaxf(mx, l[k]);
        }
        float s = 0.0f;
#pragma unroll
        for (int k = 0; k < NWAY; ++k) s += expf(l[k] - mx);
        const float ls = logf(s);
        float* o = out + (size_t)(q0 + tid) * NWAY;
#pragma unroll
        for (int k = 0; k < NWAY; ++k) o[k] = l[k] - mx - ls;
    }
}

// ---------------- launch --------------------------------------------------------
extern "C" void kernel_launch(void* const* d_in, const int* in_sizes, int n_in,
                              void* d_out, int out_size) {
    (void)in_sizes; (void)out_size;
    const float* support_x = (const float*)d_in[0];
    const void*  support_y = d_in[1];
    const float* query_x   = (const float*)d_in[2];
    int base = (n_in >= 8) ? 4 : 3;   // n_way scalar may or may not be marshalled
    const float* W1 = (const float*)d_in[base + 0];
    const float* b1 = (const float*)d_in[base + 1];
    const float* W2 = (const float*)d_in[base + 2];
    const float* b2 = (const float*)d_in[base + 3];
    float* out = (float*)d_out;

    pairs_kernel<<<dim3(NQRY / QTILE, NSB), 256>>>(query_x, support_x, W1, b1, W2,
                                                   b2, support_y, out);
}

// round 16
// speedup vs baseline: 1.0714x; 1.0006x over previous
#include <cuda_runtime.h>
#include <cuda_fp16.h>
#include <cstdint>
#include <math.h>

// Problem constants (fixed by setup_inputs).
#define NSUP   1024
#define NQRY   1024
#define DDIM   128
#define HDIM   64
#define NWAY   8
#define QTILE  128
#define SCHUNK 57
#define NSB    18           // ceil(1024/57); grid 8 x 18 = 144 CTAs = exactly 1 wave

// Per-CTA partial sums: [qb*NSB + sb][class][q] -- fully written, no init needed.
__device__ float    g_part[(NQRY / QTILE) * NSB * NWAY * QTILE];
// Per-q-column completion tickets. atomicInc with wrap NSB-1 -> back to 0 after
// every launch (exactly NSB increments per column), so graph replays see 0.
__device__ unsigned g_tick[NQRY / QTILE];

// ---------------- helpers ----------------------------------------------------
__device__ __forceinline__ uint32_t h2u(__half2 h) {
    return *reinterpret_cast<uint32_t*>(&h);
}
__device__ __forceinline__ uint32_t absdiff2(uint32_t q, __half2 s) {
    __half2 hq = *reinterpret_cast<__half2*>(&q);
    return h2u(__habs2(__hsub2(hq, s)));
}
__device__ __forceinline__ void mma16816(float* d, uint32_t a0, uint32_t a1,
                                         uint32_t a2, uint32_t a3,
                                         uint32_t b0, uint32_t b1) {
    asm volatile(
        "mma.sync.aligned.m16n8k16.row.col.f32.f16.f16.f32 "
        "{%0,%1,%2,%3}, {%4,%5,%6,%7}, {%8,%9}, {%0,%1,%2,%3};"
        : "+f"(d[0]), "+f"(d[1]), "+f"(d[2]), "+f"(d[3])
        : "r"(a0), "r"(a1), "r"(a2), "r"(a3), "r"(b0), "r"(b1));
}

// ---------------- single fused kernel ------------------------------------------
// CTA: 128-q block x 57-s chunk, 256 threads, grid 8x18 = one full wave.
// Warp (mi, nj): mi = 32-row m-slice, nj = 32-col n-slice. A fragments computed
// directly in registers. Software pipeline: the epilogue of step i-1 runs while
// step i's HMMAs are in flight (double-buffered accumulators DA/DB), hiding the
// HMMA drain latency and the shfl-reduce chains.
__global__ __launch_bounds__(256, 1) void pairs_kernel(
    const float* __restrict__ qx, const float* __restrict__ sx,
    const float* __restrict__ W1, const float* __restrict__ b1,
    const float* __restrict__ w2v, const float* __restrict__ b2g,
    const void* __restrict__ sy_raw, float* __restrict__ out) {
    __shared__ __half2  s_sm[SCHUNK * 64];          // s chunk, fp16x2 (14.25KB)
    __shared__ float    accf[2 * NWAY * QTILE];     // [nj][class][q]; reused as logits
    __shared__ int      slab[SCHUNK];
    __shared__ int      s_is64;
    __shared__ unsigned s_old;
    __shared__ float    s_hist[8][NWAY];

    const int tid  = threadIdx.x;
    const int lane = tid & 31;
    const int wid  = tid >> 5;
    const int mi   = wid & 3;
    const int nj   = wid >> 2;
    const int g    = lane >> 2;       // row-in-8 group
    const int i2   = lane & 3;        // k quad position
    const int q0   = blockIdx.x * QTILE;
    const int s0   = blockIdx.y * SCHUNK;
    const int ns   = min(SCHUNK, NSUP - s0);

    if (tid == 0) s_is64 = 1;
    for (int idx = tid; idx < 2 * NWAY * QTILE; idx += 256) accf[idx] = 0.0f;
    __syncthreads();

    // int64-vs-int32 detection for support_y (odd words all zero => int64).
    const int* sy32 = (const int*)sy_raw;
    if (sy32[2 * tid + 1] != 0) atomicExch(&s_is64, 0);

    // Stage s chunk as half2 (row = 64 half2 = 256B).
    for (int idx = tid; idx < ns * 64; idx += 256) {
        int r = idx >> 6, c = idx & 63;
        float2 v = *(const float2*)(sx + (size_t)(s0 + r) * DDIM + 2 * c);
        s_sm[idx] = __floats2half2_rn(v.x, v.y);
    }
    __syncthreads();

    const int is64 = s_is64;
    const long long* sy64 = (const long long*)sy_raw;
    for (int idx = tid; idx < ns; idx += 256)
        slab[idx] = is64 ? (int)sy64[s0 + idx] : sy32[s0 + idx];

    // ---- q fragment values in registers: qh[ri][kb][h] ----
    uint32_t qh[4][8][2];
#pragma unroll
    for (int ri = 0; ri < 4; ++ri) {
        const float* qp = qx + (size_t)(q0 + mi * 32 + g + ri * 8) * DDIM + i2 * 2;
#pragma unroll
        for (int kb = 0; kb < 8; ++kb) {
            float2 v0 = *(const float2*)(qp + kb * 16);
            float2 v1 = *(const float2*)(qp + kb * 16 + 8);
            qh[ri][kb][0] = h2u(__floats2half2_rn(v0.x, v0.y));
            qh[ri][kb][1] = h2u(__floats2half2_rn(v1.x, v1.y));
        }
    }

    // ---- W1 B-fragments in registers (warp covers cols nj*32..+31) ----
    uint32_t Bf[4][8][2];
#pragma unroll
    for (int nb = 0; nb < 4; ++nb) {
        const float* wr = W1 + (size_t)(nj * 32 + nb * 8 + g) * DDIM + i2 * 2;
#pragma unroll
        for (int kb = 0; kb < 8; ++kb) {
            float2 v0 = *(const float2*)(wr + kb * 16);
            float2 v1 = *(const float2*)(wr + kb * 16 + 8);
            Bf[nb][kb][0] = h2u(__floats2half2_rn(v0.x, v0.y));
            Bf[nb][kb][1] = h2u(__floats2half2_rn(v1.x, v1.y));
        }
    }

    // ---- b1 / w2 for this thread's output columns ----
    float b1r[8], w2r[8];
#pragma unroll
    for (int nb = 0; nb < 4; ++nb)
#pragma unroll
        for (int c = 0; c < 2; ++c) {
            int col = nj * 32 + nb * 8 + i2 * 2 + c;
            b1r[nb * 2 + c] = b1[col];
            w2r[nb * 2 + c] = w2v[col];
        }

    __syncthreads();   // slab ready (s_sm already synced)

    // ---- pipelined step helpers ----
    // mma_step: init D = b1, run the 8x(kb) HMMA block for s row i.
    auto mma_step = [&](float D[2][4][4], int i) {
        const __half2* srow = s_sm + i * 64;
#pragma unroll
        for (int mb = 0; mb < 2; ++mb)
#pragma unroll
            for (int nb = 0; nb < 4; ++nb) {
                D[mb][nb][0] = b1r[nb * 2];
                D[mb][nb][1] = b1r[nb * 2 + 1];
                D[mb][nb][2] = b1r[nb * 2];
                D[mb][nb][3] = b1r[nb * 2 + 1];
            }
#pragma unroll
        for (int kb = 0; kb < 8; ++kb) {
            __half2 hs0 = srow[kb * 8 + i2];
            __half2 hs1 = srow[kb * 8 + 4 + i2];
#pragma unroll
            for (int mb = 0; mb < 2; ++mb) {
                uint32_t a0 = absdiff2(qh[2 * mb][kb][0], hs0);
                uint32_t a1 = absdiff2(qh[2 * mb + 1][kb][0], hs0);
                uint32_t a2 = absdiff2(qh[2 * mb][kb][1], hs1);
                uint32_t a3 = absdiff2(qh[2 * mb + 1][kb][1], hs1);
#pragma unroll
                for (int nb = 0; nb < 4; ++nb)
                    mma16816(D[mb][nb], a0, a1, a2, a3, Bf[nb][kb][0], Bf[nb][kb][1]);
            }
        }
    };

    // epilogue: relu-dot + quad shfl reduce + smem class accumulate for s row.
    auto epilogue = [&](float D[2][4][4], int lab) {
#pragma unroll
        for (int mb = 0; mb < 2; ++mb) {
            float p0 = 0.0f, p1 = 0.0f;
#pragma unroll
            for (int nb = 0; nb < 4; ++nb)
#pragma unroll
                for (int c = 0; c < 2; ++c) {
                    p0 = fmaf(fmaxf(D[mb][nb][c],     0.0f), w2r[nb * 2 + c], p0);
                    p1 = fmaf(fmaxf(D[mb][nb][2 + c], 0.0f), w2r[nb * 2 + c], p1);
                }
            p0 += __shfl_xor_sync(0xffffffffu, p0, 1);
            p0 += __shfl_xor_sync(0xffffffffu, p0, 2);
            p1 += __shfl_xor_sync(0xffffffffu, p1, 1);
            p1 += __shfl_xor_sync(0xffffffffu, p1, 2);
            if (i2 == 0) {
                int r0 = mi * 32 + mb * 16 + g;
                accf[nj * (NWAY * QTILE) + lab * QTILE + r0]     += p0;
                accf[nj * (NWAY * QTILE) + lab * QTILE + r0 + 8] += p1;
            }
        }
    };

    // ---- main loop: epilogue runs one step behind the MMA block ----
    float DA[2][4][4], DB[2][4][4];
    mma_step(DA, 0);
    int i = 1;
    for (; i + 1 < ns; i += 2) {
        mma_step(DB, i);
        epilogue(DA, slab[i - 1]);
        mma_step(DA, i + 1);
        epilogue(DB, slab[i]);
    }
    if (i < ns) {                    // ns even: one step left
        mma_step(DB, i);
        epilogue(DA, slab[i - 1]);
        epilogue(DB, slab[i]);
    } else {                         // ns odd: drain
        epilogue(DA, slab[ns - 1]);
    }

    __syncthreads();
    // Flush per-CTA partials (merge n-halves); unique g_part slice per CTA.
    float* dst = g_part + (size_t)(blockIdx.x * NSB + blockIdx.y) * (NWAY * QTILE);
    for (int idx = tid; idx < NWAY * QTILE; idx += 256)
        dst[idx] = accf[idx] + accf[NWAY * QTILE + idx];
    __syncthreads();

    // Ticket: last CTA in this q-column becomes the reducer.
    if (tid == 0) {
        __threadfence();
        s_old = atomicInc(&g_tick[blockIdx.x], NSB - 1);
    }
    __syncthreads();
    if (s_old != NSB - 1) return;

    // ================= reducer path (one CTA per q-column) ==================
    // Label histogram: warp w covers labels [w*128, w*128+128) in registers.
    {
        float cnt[NWAY];
#pragma unroll
        for (int m = 0; m < NWAY; ++m) cnt[m] = 0.0f;
#pragma unroll
        for (int k = 0; k < 4; ++k) {
            int idx = wid * 128 + k * 32 + lane;
            int lab = is64 ? (int)sy64[idx] : sy32[idx];
#pragma unroll
            for (int m = 0; m < NWAY; ++m) cnt[m] += (lab == m) ? 1.0f : 0.0f;
        }
#pragma unroll
        for (int m = 0; m < NWAY; ++m) {
            cnt[m] += __shfl_xor_sync(0xffffffffu, cnt[m], 16);
            cnt[m] += __shfl_xor_sync(0xffffffffu, cnt[m], 8);
            cnt[m] += __shfl_xor_sync(0xffffffffu, cnt[m], 4);
            cnt[m] += __shfl_xor_sync(0xffffffffu, cnt[m], 2);
            cnt[m] += __shfl_xor_sync(0xffffffffu, cnt[m], 1);
        }
        if (lane < NWAY) s_hist[wid][lane] = cnt[lane];
    }
    __syncthreads();

    // Reduce 18 partials per (q, class); 4 outputs per thread, coalesced over q.
    float* logit = accf;             // reuse smem: [q][class]
    const float b2v = b2g[0];
#pragma unroll
    for (int j = 0; j < 4; ++j) {
        const int idx = tid + 256 * j;
        const int c = idx >> 7, qi = idx & 127;
        const float* p = g_part + ((size_t)(blockIdx.x * NSB) * NWAY + c) * QTILE + qi;
        float a = 0.0f;
#pragma unroll
        for (int sb = 0; sb < NSB; ++sb) a += p[(size_t)sb * (NWAY * QTILE)];
        float cn = 0.0f;
#pragma unroll
        for (int w = 0; w < 8; ++w) cn += s_hist[w][c];
        logit[qi * NWAY + c] = a / cn + b2v;
    }
    __syncthreads();

    // log_softmax: one q per thread (threads 0..127).
    if (tid < QTILE) {
        float l[NWAY], mx = -1e30f;
#pragma unroll
        for (int k = 0; k < NWAY; ++k) {
            l[k] = logit[tid * NWAY + k];
            mx = fmaxf(mx, l[k]);
        }
        float s = 0.0f;
#pragma unroll
        for (int k = 0; k < NWAY; ++k) s += expf(l[k] - mx);
        const float ls = logf(s);
        float* o = out + (size_t)(q0 + tid) * NWAY;
#pragma unroll
        for (int k = 0; k < NWAY; ++k) o[k] = l[k] - mx - ls;
    }
}

// ---------------- launch --------------------------------------------------------
extern "C" void kernel_launch(void* const* d_in, const int* in_sizes, int n_in,
                              void* d_out, int out_size) {
    (void)in_sizes; (void)out_size;
    const float* support_x = (const float*)d_in[0];
    const void*  support_y = d_in[1];
    const float* query_x   = (const float*)d_in[2];
    int base = (n_in >= 8) ? 4 : 3;   // n_way scalar may or may not be marshalled
    const float* W1 = (const float*)d_in[base + 0];
    const float* b1 = (const float*)d_in[base + 1];
    const float* W2 = (const float*)d_in[base + 2];
    const float* b2 = (const float*)d_in[base + 3];
    float* out = (float*)d_out;

    pairs_kernel<<<dim3(NQRY / QTILE, NSB), 256>>>(query_x, support_x, W1, b1, W2,
                                                   b2, support_y, out);
}